// round 8
// baseline (speedup 1.0000x reference)
#include <cuda_runtime.h>
#include <math_constants.h>

// GAT autoencoder, CSR-gather formulation.
// Layers: 64->64 relu, 64->32 [h out], relu, 32->64 relu, 64->64 [out].
// Outputs concatenated: out [N*64] then h [N*32].

#define MAXN 50000
#define MAXE 800000
#define MAXET (MAXE + MAXN)
#define MAXBLK 64

// ---------------- scratch ----------------
__device__ __align__(16) float g_featA[MAXN * 64];
__device__ __align__(16) float g_featB[MAXN * 64];
__device__ __align__(16) float g_h[MAXN * 64];
__device__ float g_ssrc[MAXN];
__device__ float g_sdst[MAXN];
__device__ float g_e[MAXET];
__device__ int g_src[MAXET];
__device__ int g_dst[MAXET];
__device__ int g_adj[MAXET];
__device__ int g_roff[MAXN + 1];
__device__ int g_cnt[MAXN];
__device__ int g_cur[MAXN];
__device__ int g_bt[MAXBLK];
__device__ int g_boff[MAXBLK];
__device__ int g_is64;

__device__ __forceinline__ const float* pick_src(int sel, const float* ext) {
    if (sel == 1) return g_featA;
    if (sel == 2) return g_featB;
    return ext;
}
__device__ __forceinline__ float* pick_dst(int sel) {
    if (sel == 1) return g_featA;
    if (sel == 2) return g_featB;
    return nullptr;
}

// packed f32x2 helpers (Blackwell FFMA2 path)
__device__ __forceinline__ unsigned long long splat2(float a) {
    unsigned long long r;
    asm("mov.b64 %0,{%1,%1};" : "=l"(r) : "f"(a));
    return r;
}
__device__ __forceinline__ void ffma2(unsigned long long& d,
                                      unsigned long long a, float wx, float wy) {
    unsigned long long w;
    asm("mov.b64 %0,{%1,%2};" : "=l"(w) : "f"(wx), "f"(wy));
    asm("fma.rn.f32x2 %0,%1,%2,%0;" : "+l"(d) : "l"(a), "l"(w));
}
__device__ __forceinline__ void unpack2(unsigned long long v, float& lo, float& hi) {
    asm("mov.b64 {%0,%1},%2;" : "=f"(lo), "=f"(hi) : "l"(v));
}

// ---------------- graph prep ----------------

// parallel dtype detect: int64 little-endian ids < 2^31 => odd words all 0
__global__ void k_detect(const unsigned int* __restrict__ w, int nelem) {
    __shared__ int bad;
    if (threadIdx.x == 0) bad = 0;
    __syncthreads();
    int idx = 2 * (int)threadIdx.x + 1;  // 128 threads -> odd words 1..255
    if (idx < 2 * nelem && idx < 256 && w[idx] != 0) atomicOr(&bad, 1);
    __syncthreads();
    if (threadIdx.x == 0) g_is64 = !bad;
}

__global__ void k_convert(const void* __restrict__ ei, int eraw, int n) {
    int i = blockIdx.x * 256 + threadIdx.x;
    int etot = eraw + n;
    if (i >= etot) return;
    if (i < eraw) {
        int s, d;
        if (g_is64) {
            const long long* p = (const long long*)ei;
            s = (int)p[i];
            d = (int)p[eraw + i];
        } else {
            const int* p = (const int*)ei;
            s = p[i];
            d = p[eraw + i];
        }
        s = s < 0 ? 0 : (s >= n ? n - 1 : s);
        d = d < 0 ? 0 : (d >= n ? n - 1 : d);
        g_src[i] = s;
        g_dst[i] = d;
    } else {
        int v = i - eraw;
        g_src[i] = v;
        g_dst[i] = v;
    }
}

__global__ void k_zero(int n) {
    int i = blockIdx.x * 256 + threadIdx.x;
    if (i < n) g_cnt[i] = 0;
}

__global__ void k_hist(int etot) {
    int i = blockIdx.x * 256 + threadIdx.x;
    if (i < etot) atomicAdd(&g_cnt[g_dst[i]], 1);
}

__global__ void k_scan_bt(int n) {
    int base = blockIdx.x * 1024;
    int i0 = base + threadIdx.x * 4;
    int t = 0;
#pragma unroll
    for (int c = 0; c < 4; c++) t += (i0 + c < n) ? g_cnt[i0 + c] : 0;
    int lane = threadIdx.x & 31, wid = threadIdx.x >> 5;
#pragma unroll
    for (int off = 16; off; off >>= 1) t += __shfl_xor_sync(~0u, t, off);
    __shared__ int ws[8];
    if (lane == 0) ws[wid] = t;
    __syncthreads();
    if (threadIdx.x == 0) {
        int s = 0;
#pragma unroll
        for (int w = 0; w < 8; w++) s += ws[w];
        g_bt[blockIdx.x] = s;
    }
}

__global__ void k_scan_mid(int nblk, int n) {
    int lane = threadIdx.x;
    int carry = 0;
    for (int base = 0; base < nblk; base += 32) {
        int i = base + lane;
        int v = (i < nblk) ? g_bt[i] : 0;
        int incl = v;
#pragma unroll
        for (int off = 1; off < 32; off <<= 1) {
            int t = __shfl_up_sync(~0u, incl, off);
            if (lane >= off) incl += t;
        }
        if (i < nblk) g_boff[i] = carry + incl - v;
        carry += __shfl_sync(~0u, incl, 31);
    }
    if (lane == 0) g_roff[n] = carry;
}

__global__ void k_scan_wr(int n) {
    int base = blockIdx.x * 1024;
    int i0 = base + threadIdx.x * 4;
    int v[4], tsum = 0;
#pragma unroll
    for (int c = 0; c < 4; c++) {
        v[c] = (i0 + c < n) ? g_cnt[i0 + c] : 0;
        tsum += v[c];
    }
    int lane = threadIdx.x & 31, wid = threadIdx.x >> 5;
    int incl = tsum;
#pragma unroll
    for (int off = 1; off < 32; off <<= 1) {
        int t = __shfl_up_sync(~0u, incl, off);
        if (lane >= off) incl += t;
    }
    __shared__ int ws[8];
    if (lane == 31) ws[wid] = incl;
    __syncthreads();
    int woff = 0;
    for (int w = 0; w < wid; w++) woff += ws[w];
    int ex = g_boff[blockIdx.x] + woff + incl - tsum;
#pragma unroll
    for (int c = 0; c < 4; c++) {
        if (i0 + c < n) {
            g_roff[i0 + c] = ex;
            g_cur[i0 + c] = ex;
            ex += v[c];
        }
    }
}

__global__ void k_scatter(int etot) {
    int i = blockIdx.x * 256 + threadIdx.x;
    if (i >= etot) return;
    int pos = atomicAdd(&g_cur[g_dst[i]], 1);
    g_adj[pos] = g_src[i];
}

// ---------------- fused gemm + attention scores ----------------
// 4 lanes per row; lane computes DO/4 contiguous cols with packed f32x2 FMA.
template <int DI, int DO>
__global__ void k_gemm_sc(int xsel, const float* __restrict__ xext,
                          const float* __restrict__ W,
                          const float* __restrict__ as_,
                          const float* __restrict__ ad_, int n) {
    const int CP = DO / 8;  // packed accumulators per lane
    __shared__ float Ws[DI * DO];
    for (int i = threadIdx.x; i < DI * DO; i += 256) Ws[i] = W[i];
    __syncthreads();
    int t = blockIdx.x * 256 + threadIdx.x;
    int row0 = t >> 2;
    bool valid = row0 < n;
    int row = valid ? row0 : n - 1;
    int sub = t & 3;  // col quarter
    const float* x = pick_src(xsel, xext) + row * DI;
    unsigned long long acc[CP];
#pragma unroll
    for (int c = 0; c < CP; c++) acc[c] = 0ull;
#pragma unroll
    for (int k0 = 0; k0 < DI; k0 += 4) {
        float4 xv = __ldg(reinterpret_cast<const float4*>(x) + k0 / 4);
#pragma unroll
        for (int kk = 0; kk < 4; kk++) {
            float xk = kk == 0 ? xv.x : kk == 1 ? xv.y : kk == 2 ? xv.z : xv.w;
            unsigned long long av = splat2(xk);
            const float4* wr = reinterpret_cast<const float4*>(
                Ws + (k0 + kk) * DO + sub * (DO / 4));
#pragma unroll
            for (int c = 0; c < CP / 2; c++) {
                float4 w = wr[c];
                ffma2(acc[2 * c + 0], av, w.x, w.y);
                ffma2(acc[2 * c + 1], av, w.z, w.w);
            }
        }
    }
    // unpack, write h, partial score dots
    float vs[DO / 4];
#pragma unroll
    for (int c = 0; c < CP; c++) unpack2(acc[c], vs[2 * c], vs[2 * c + 1]);
    if (valid) {
        float4* hw = reinterpret_cast<float4*>(g_h + row * DO + sub * (DO / 4));
#pragma unroll
        for (int q = 0; q < DO / 16; q++)
            hw[q] = make_float4(vs[4 * q], vs[4 * q + 1], vs[4 * q + 2], vs[4 * q + 3]);
    }
    float ss = 0.f, sd = 0.f;
#pragma unroll
    for (int c = 0; c < DO / 4; c++) {
        ss = fmaf(vs[c], __ldg(as_ + sub * (DO / 4) + c), ss);
        sd = fmaf(vs[c], __ldg(ad_ + sub * (DO / 4) + c), sd);
    }
    ss += __shfl_xor_sync(~0u, ss, 1);
    sd += __shfl_xor_sync(~0u, sd, 1);
    ss += __shfl_xor_sync(~0u, ss, 2);
    sd += __shfl_xor_sync(~0u, sd, 2);
    if (sub == 0 && valid) {
        g_ssrc[row] = ss;
        g_sdst[row] = sd;
    }
}

// per-CSR-slot source score prefetch (flat, full MLP, coalesced writes)
__global__ void k_edgepre(int etot) {
    int j = blockIdx.x * 256 + threadIdx.x;
    if (j < etot) g_e[j] = __ldg(&g_ssrc[__ldg(&g_adj[j])]);
}

// ---------------- fused softmax + aggregation ----------------
// DO/32 warps per node (col halves). Within a warp: 4 edge-groups of 8
// lanes; each group covers 32 cols (8 x float4) and strides edges by 4,
// 2-edge unrolled -> 8 h-row loads in flight per warp.
template <int DO>
__global__ void k_gather(const float* __restrict__ b, int featsel,
                         float* __restrict__ raw, int n) {
    const int WPN = DO / 32;
    int gw = (blockIdx.x * blockDim.x + threadIdx.x) >> 5;
    int d = gw / WPN;
    int cw = gw - d * WPN;  // col half
    int lane = threadIdx.x & 31;
    int grp = lane >> 3;
    int gl = lane & 7;
    if (d >= n) return;
    int r0 = __ldg(&g_roff[d]);
    int r1 = __ldg(&g_roff[d + 1]);
    float sd = g_sdst[d];

    // pass 1: segment max over contiguous e (coalesced)
    float m = -CUDART_INF_F;
    for (int j = r0 + lane; j < r1; j += 32) {
        float e = __ldg(&g_e[j]) + sd;
        e = e > 0.f ? e : 0.2f * e;
        m = fmaxf(m, e);
    }
#pragma unroll
    for (int off = 16; off; off >>= 1)
        m = fmaxf(m, __shfl_xor_sync(0xFFFFFFFFu, m, off));

    // pass 2
    const float4* hb = reinterpret_cast<const float4*>(g_h);
    const int RS = DO / 4;           // row stride in float4
    int cbase = cw * 8 + gl;         // this lane's float4 within row
    float den = 0.f;
    float4 acc = make_float4(0.f, 0.f, 0.f, 0.f);
    int j = r0 + grp;
    for (; j + 4 < r1; j += 8) {
        int s0 = __ldg(&g_adj[j]);
        int s1 = __ldg(&g_adj[j + 4]);
        float e0 = __ldg(&g_e[j]) + sd;
        float e1 = __ldg(&g_e[j + 4]) + sd;
        float4 h0 = __ldg(hb + s0 * RS + cbase);
        float4 h1 = __ldg(hb + s1 * RS + cbase);
        e0 = e0 > 0.f ? e0 : 0.2f * e0;
        e1 = e1 > 0.f ? e1 : 0.2f * e1;
        float x0 = __expf(e0 - m);
        float x1 = __expf(e1 - m);
        den += x0 + x1;
        acc.x = fmaf(x0, h0.x, acc.x); acc.y = fmaf(x0, h0.y, acc.y);
        acc.z = fmaf(x0, h0.z, acc.z); acc.w = fmaf(x0, h0.w, acc.w);
        acc.x = fmaf(x1, h1.x, acc.x); acc.y = fmaf(x1, h1.y, acc.y);
        acc.z = fmaf(x1, h1.z, acc.z); acc.w = fmaf(x1, h1.w, acc.w);
    }
    if (j < r1) {
        int s0 = __ldg(&g_adj[j]);
        float e0 = __ldg(&g_e[j]) + sd;
        float4 h0 = __ldg(hb + s0 * RS + cbase);
        e0 = e0 > 0.f ? e0 : 0.2f * e0;
        float x0 = __expf(e0 - m);
        den += x0;
        acc.x = fmaf(x0, h0.x, acc.x); acc.y = fmaf(x0, h0.y, acc.y);
        acc.z = fmaf(x0, h0.z, acc.z); acc.w = fmaf(x0, h0.w, acc.w);
    }
    // merge the 4 groups
#pragma unroll
    for (int off = 8; off <= 16; off <<= 1) {
        den += __shfl_xor_sync(0xFFFFFFFFu, den, off);
        acc.x += __shfl_xor_sync(0xFFFFFFFFu, acc.x, off);
        acc.y += __shfl_xor_sync(0xFFFFFFFFu, acc.y, off);
        acc.z += __shfl_xor_sync(0xFFFFFFFFu, acc.z, off);
        acc.w += __shfl_xor_sync(0xFFFFFFFFu, acc.w, off);
    }
    if (grp == 0) {
        float inv = 1.f / (den + 1e-16f);
        float4 bb = __ldg(reinterpret_cast<const float4*>(b) + cbase);
        float4 v = make_float4(acc.x * inv + bb.x, acc.y * inv + bb.y,
                               acc.z * inv + bb.z, acc.w * inv + bb.w);
        if (raw) reinterpret_cast<float4*>(raw + d * DO)[cbase] = v;
        float* feat = pick_dst(featsel);
        if (feat) {
            float4 r = make_float4(fmaxf(v.x, 0.f), fmaxf(v.y, 0.f),
                                   fmaxf(v.z, 0.f), fmaxf(v.w, 0.f));
            reinterpret_cast<float4*>(feat + d * DO)[cbase] = r;
        }
    }
}

// ---------------- launch ----------------
extern "C" void kernel_launch(void* const* d_in, const int* in_sizes, int n_in,
                              void* d_out, int out_size) {
    const float* x = (const float*)d_in[0];
    const void* ei = d_in[1];
    const float* w1 = (const float*)d_in[2];
    const float* as1 = (const float*)d_in[3];
    const float* ad1 = (const float*)d_in[4];
    const float* b1 = (const float*)d_in[5];
    const float* w2 = (const float*)d_in[6];
    const float* as2 = (const float*)d_in[7];
    const float* ad2 = (const float*)d_in[8];
    const float* b2 = (const float*)d_in[9];
    const float* w3 = (const float*)d_in[10];
    const float* as3 = (const float*)d_in[11];
    const float* ad3 = (const float*)d_in[12];
    const float* b3 = (const float*)d_in[13];
    const float* w4 = (const float*)d_in[14];
    const float* as4 = (const float*)d_in[15];
    const float* ad4 = (const float*)d_in[16];
    const float* b4 = (const float*)d_in[17];

    int n = in_sizes[0] / 64;
    int eraw = in_sizes[1] / 2;
    int etot = eraw + n;

    float* out_sec = (float*)d_out;         // [n*64]
    float* h_sec = (float*)d_out + n * 64;  // [n*32]

    int nbE = (etot + 255) / 256;
    int nbN = (n + 255) / 256;
    int nbG = (n * 4 + 255) / 256;           // gemm: 4 lanes/row
    int nbW64 = (n * 2 * 32 + 511) / 512;    // gather DO=64: 2 warps/node
    int nbW32 = (n * 32 + 511) / 512;        // gather DO=32: 1 warp/node
    int nblk = (n + 1023) / 1024;

    // graph prep (once per call)
    k_detect<<<1, 128>>>((const unsigned int*)ei, in_sizes[1]);
    k_convert<<<nbE, 256>>>(ei, eraw, n);
    k_zero<<<nbN, 256>>>(n);
    k_hist<<<nbE, 256>>>(etot);
    k_scan_bt<<<nblk, 256>>>(n);
    k_scan_mid<<<1, 32>>>(nblk, n);
    k_scan_wr<<<nblk, 256>>>(n);
    k_scatter<<<nbE, 256>>>(etot);

    // layer 1: x 64->64, relu -> featA
    k_gemm_sc<64, 64><<<nbG, 256>>>(0, x, w1, as1, ad1, n);
    k_edgepre<<<nbE, 256>>>(etot);
    k_gather<64><<<nbW64, 512>>>(b1, 1, nullptr, n);

    // layer 2: featA 64->32, raw h -> d_out, relu -> featB
    k_gemm_sc<64, 32><<<nbG, 256>>>(1, nullptr, w2, as2, ad2, n);
    k_edgepre<<<nbE, 256>>>(etot);
    k_gather<32><<<nbW32, 512>>>(b2, 2, h_sec, n);

    // layer 3: featB 32->64, relu -> featA
    k_gemm_sc<32, 64><<<nbG, 256>>>(2, nullptr, w3, as3, ad3, n);
    k_edgepre<<<nbE, 256>>>(etot);
    k_gather<64><<<nbW64, 512>>>(b3, 1, nullptr, n);

    // layer 4: featA 64->64, raw -> d_out
    k_gemm_sc<64, 64><<<nbG, 256>>>(1, nullptr, w4, as4, ad4, n);
    k_edgepre<<<nbE, 256>>>(etot);
    k_gather<64><<<nbW64, 512>>>(b4, 0, out_sec, n);
}

// round 9
// speedup vs baseline: 1.2308x; 1.2308x over previous
#include <cuda_runtime.h>
#include <math_constants.h>

// GAT autoencoder, CSR-gather formulation.
// Layers: 64->64 relu, 64->32 [h out], relu, 32->64 relu, 64->64 [out].
// Outputs concatenated: out [N*64] then h [N*32].

#define MAXN 50000
#define MAXE 800000
#define MAXET (MAXE + MAXN)
#define MAXBLK 64

// ---------------- scratch ----------------
__device__ __align__(16) float g_featA[MAXN * 64];
__device__ __align__(16) float g_featB[MAXN * 64];
__device__ __align__(16) float g_h[MAXN * 64];
__device__ float g_ssrc[MAXN];
__device__ float g_sdst[MAXN];
__device__ float g_e[MAXET];
__device__ int g_src[MAXET];
__device__ int g_dst[MAXET];
__device__ int g_adj[MAXET];
__device__ int g_roff[MAXN + 1];
__device__ int g_cnt[MAXN];
__device__ int g_cur[MAXN];
__device__ int g_bt[MAXBLK];
__device__ int g_boff[MAXBLK];
__device__ int g_is64;

__device__ __forceinline__ const float* pick_src(int sel, const float* ext) {
    if (sel == 1) return g_featA;
    if (sel == 2) return g_featB;
    return ext;
}
__device__ __forceinline__ float* pick_dst(int sel) {
    if (sel == 1) return g_featA;
    if (sel == 2) return g_featB;
    return nullptr;
}

// ---------------- graph prep ----------------

// parallel dtype detect: int64 little-endian ids < 2^31 => odd words all 0
__global__ void k_detect(const unsigned int* __restrict__ w, int nelem) {
    __shared__ int bad;
    if (threadIdx.x == 0) bad = 0;
    __syncthreads();
    int idx = 2 * (int)threadIdx.x + 1;  // 128 threads -> odd words 1..255
    if (idx < 2 * nelem && idx < 256 && w[idx] != 0) atomicOr(&bad, 1);
    __syncthreads();
    if (threadIdx.x == 0) g_is64 = !bad;
}

__global__ void k_convert(const void* __restrict__ ei, int eraw, int n) {
    int i = blockIdx.x * 256 + threadIdx.x;
    int etot = eraw + n;
    if (i >= etot) return;
    if (i < eraw) {
        int s, d;
        if (g_is64) {
            const long long* p = (const long long*)ei;
            s = (int)p[i];
            d = (int)p[eraw + i];
        } else {
            const int* p = (const int*)ei;
            s = p[i];
            d = p[eraw + i];
        }
        s = s < 0 ? 0 : (s >= n ? n - 1 : s);
        d = d < 0 ? 0 : (d >= n ? n - 1 : d);
        g_src[i] = s;
        g_dst[i] = d;
    } else {
        int v = i - eraw;
        g_src[i] = v;
        g_dst[i] = v;
    }
}

__global__ void k_zero(int n) {
    int i = blockIdx.x * 256 + threadIdx.x;
    if (i < n) g_cnt[i] = 0;
}

__global__ void k_hist(int etot) {
    int i = blockIdx.x * 256 + threadIdx.x;
    if (i < etot) atomicAdd(&g_cnt[g_dst[i]], 1);
}

// --- two-level exclusive scan of g_cnt ---
__global__ void k_scan_bt(int n) {
    int base = blockIdx.x * 1024;
    int i0 = base + threadIdx.x * 4;
    int t = 0;
#pragma unroll
    for (int c = 0; c < 4; c++) t += (i0 + c < n) ? g_cnt[i0 + c] : 0;
    int lane = threadIdx.x & 31, wid = threadIdx.x >> 5;
#pragma unroll
    for (int off = 16; off; off >>= 1) t += __shfl_xor_sync(~0u, t, off);
    __shared__ int ws[8];
    if (lane == 0) ws[wid] = t;
    __syncthreads();
    if (threadIdx.x == 0) {
        int s = 0;
#pragma unroll
        for (int w = 0; w < 8; w++) s += ws[w];
        g_bt[blockIdx.x] = s;
    }
}

__global__ void k_scan_mid(int nblk, int n) {
    int lane = threadIdx.x;
    int carry = 0;
    for (int base = 0; base < nblk; base += 32) {
        int i = base + lane;
        int v = (i < nblk) ? g_bt[i] : 0;
        int incl = v;
#pragma unroll
        for (int off = 1; off < 32; off <<= 1) {
            int t = __shfl_up_sync(~0u, incl, off);
            if (lane >= off) incl += t;
        }
        if (i < nblk) g_boff[i] = carry + incl - v;
        carry += __shfl_sync(~0u, incl, 31);
    }
    if (lane == 0) g_roff[n] = carry;
}

__global__ void k_scan_wr(int n) {
    int base = blockIdx.x * 1024;
    int i0 = base + threadIdx.x * 4;
    int v[4], tsum = 0;
#pragma unroll
    for (int c = 0; c < 4; c++) {
        v[c] = (i0 + c < n) ? g_cnt[i0 + c] : 0;
        tsum += v[c];
    }
    int lane = threadIdx.x & 31, wid = threadIdx.x >> 5;
    int incl = tsum;
#pragma unroll
    for (int off = 1; off < 32; off <<= 1) {
        int t = __shfl_up_sync(~0u, incl, off);
        if (lane >= off) incl += t;
    }
    __shared__ int ws[8];
    if (lane == 31) ws[wid] = incl;
    __syncthreads();
    int woff = 0;
    for (int w = 0; w < wid; w++) woff += ws[w];
    int ex = g_boff[blockIdx.x] + woff + incl - tsum;
#pragma unroll
    for (int c = 0; c < 4; c++) {
        if (i0 + c < n) {
            g_roff[i0 + c] = ex;
            g_cur[i0 + c] = ex;
            ex += v[c];
        }
    }
}

__global__ void k_scatter(int etot) {
    int i = blockIdx.x * 256 + threadIdx.x;
    if (i >= etot) return;
    int pos = atomicAdd(&g_cur[g_dst[i]], 1);
    g_adj[pos] = g_src[i];
}

// ---------------- fused gemm + attention scores ----------------
template <int DI, int DO>
__global__ void k_gemm_sc(int xsel, const float* __restrict__ xext,
                          const float* __restrict__ W,
                          const float* __restrict__ as_,
                          const float* __restrict__ ad_, int n) {
    __shared__ float Ws[DI * DO];
    for (int i = threadIdx.x; i < DI * DO; i += blockDim.x) Ws[i] = W[i];
    __syncthreads();
    int row = (blockIdx.x * blockDim.x + threadIdx.x) >> 5;
    int lane = threadIdx.x & 31;
    if (row >= n) return;
    const float* x = pick_src(xsel, xext) + row * DI;
    float acc0 = 0.f, acc1 = 0.f;
#pragma unroll
    for (int k0 = 0; k0 < DI; k0 += 32) {
        float xv = x[k0 + lane];
#pragma unroll
        for (int kk = 0; kk < 32; kk++) {
            float xk = __shfl_sync(0xFFFFFFFFu, xv, kk);
            acc0 = fmaf(xk, Ws[(k0 + kk) * DO + lane], acc0);
            if (DO == 64) acc1 = fmaf(xk, Ws[(k0 + kk) * DO + lane + 32], acc1);
        }
    }
    g_h[row * DO + lane] = acc0;
    if (DO == 64) g_h[row * DO + lane + 32] = acc1;
    float ss = acc0 * __ldg(as_ + lane);
    float sd = acc0 * __ldg(ad_ + lane);
    if (DO == 64) {
        ss = fmaf(acc1, __ldg(as_ + lane + 32), ss);
        sd = fmaf(acc1, __ldg(ad_ + lane + 32), sd);
    }
#pragma unroll
    for (int off = 16; off; off >>= 1) {
        ss += __shfl_xor_sync(0xFFFFFFFFu, ss, off);
        sd += __shfl_xor_sync(0xFFFFFFFFu, sd, off);
    }
    if (lane == 0) {
        g_ssrc[row] = ss;
        g_sdst[row] = sd;
    }
}

// per-CSR-slot source score prefetch (flat, full MLP, coalesced writes)
__global__ void k_edgepre(int etot) {
    int j = blockIdx.x * 256 + threadIdx.x;
    if (j < etot) g_e[j] = __ldg(&g_ssrc[__ldg(&g_adj[j])]);
}

// ---------------- fused softmax + aggregation ----------------
// warp per dst node; two half-warps process even/odd edges, 2-edge unroll
// within each half (4 independent h-row loads in flight per warp).
template <int DO>
__global__ void k_gather(const float* __restrict__ b, int featsel,
                         float* __restrict__ raw, int n) {
    const int C = DO / 16;  // 4 (DO=64) or 2 (DO=32)
    int d = (blockIdx.x * blockDim.x + threadIdx.x) >> 5;
    int lane = threadIdx.x & 31;
    int half = lane >> 4, l16 = lane & 15;
    if (d >= n) return;
    int r0 = __ldg(&g_roff[d]);
    int r1 = __ldg(&g_roff[d + 1]);
    float sd = g_sdst[d];

    // pass 1: segment max over contiguous e (coalesced)
    float m = -CUDART_INF_F;
    for (int j = r0 + lane; j < r1; j += 32) {
        float e = __ldg(&g_e[j]) + sd;
        e = e > 0.f ? e : 0.2f * e;
        m = fmaxf(m, e);
    }
#pragma unroll
    for (int off = 16; off; off >>= 1)
        m = fmaxf(m, __shfl_xor_sync(0xFFFFFFFFu, m, off));

    // pass 2: each half-warp handles alternating edges, unrolled x2
    float den = 0.f;
    float acc[C];
#pragma unroll
    for (int c = 0; c < C; c++) acc[c] = 0.f;
    int j = r0 + half;
    for (; j + 2 < r1; j += 4) {
        int s0 = __ldg(&g_adj[j]);
        int s1 = __ldg(&g_adj[j + 2]);
        float e0 = __ldg(&g_e[j]) + sd;
        float e1 = __ldg(&g_e[j + 2]) + sd;
        float hv0[C], hv1[C];
        if (C == 4) {
            float4 t0 = __ldg(reinterpret_cast<const float4*>(g_h + s0 * DO) + l16);
            float4 t1 = __ldg(reinterpret_cast<const float4*>(g_h + s1 * DO) + l16);
            hv0[0] = t0.x; hv0[1] = t0.y; hv0[2] = t0.z; hv0[3] = t0.w;
            hv1[0] = t1.x; hv1[1] = t1.y; hv1[2] = t1.z; hv1[3] = t1.w;
        } else {
            float2 t0 = __ldg(reinterpret_cast<const float2*>(g_h + s0 * DO) + l16);
            float2 t1 = __ldg(reinterpret_cast<const float2*>(g_h + s1 * DO) + l16);
            hv0[0] = t0.x; hv0[1] = t0.y;
            hv1[0] = t1.x; hv1[1] = t1.y;
        }
        e0 = e0 > 0.f ? e0 : 0.2f * e0;
        e1 = e1 > 0.f ? e1 : 0.2f * e1;
        float x0 = __expf(e0 - m);
        float x1 = __expf(e1 - m);
        den += x0 + x1;
#pragma unroll
        for (int c = 0; c < C; c++) {
            acc[c] = fmaf(x0, hv0[c], acc[c]);
            acc[c] = fmaf(x1, hv1[c], acc[c]);
        }
    }
    if (j < r1) {
        int s = __ldg(&g_adj[j]);
        float e = __ldg(&g_e[j]) + sd;
        e = e > 0.f ? e : 0.2f * e;
        float ex = __expf(e - m);
        den += ex;
        float hv[C];
        if (C == 4) {
            float4 t = __ldg(reinterpret_cast<const float4*>(g_h + s * DO) + l16);
            hv[0] = t.x; hv[1] = t.y; hv[2] = t.z; hv[3] = t.w;
        } else {
            float2 t = __ldg(reinterpret_cast<const float2*>(g_h + s * DO) + l16);
            hv[0] = t.x; hv[1] = t.y;
        }
#pragma unroll
        for (int c = 0; c < C; c++) acc[c] = fmaf(ex, hv[c], acc[c]);
    }
    // merge the two halves
    den += __shfl_xor_sync(0xFFFFFFFFu, den, 16);
#pragma unroll
    for (int c = 0; c < C; c++) acc[c] += __shfl_xor_sync(0xFFFFFFFFu, acc[c], 16);

    if (half == 0) {
        float inv = 1.f / (den + 1e-16f);
        float v[C];
#pragma unroll
        for (int c = 0; c < C; c++)
            v[c] = acc[c] * inv + __ldg(b + l16 * C + c);
        float* feat = pick_dst(featsel);
        if (raw) {
            if (C == 4)
                reinterpret_cast<float4*>(raw + d * DO)[l16] =
                    make_float4(v[0], v[1], v[2], v[3]);
            else
                reinterpret_cast<float2*>(raw + d * DO)[l16] =
                    make_float2(v[0], v[1]);
        }
        if (feat) {
#pragma unroll
            for (int c = 0; c < C; c++) v[c] = v[c] > 0.f ? v[c] : 0.f;
            if (C == 4)
                reinterpret_cast<float4*>(feat + d * DO)[l16] =
                    make_float4(v[0], v[1], v[2], v[3]);
            else
                reinterpret_cast<float2*>(feat + d * DO)[l16] =
                    make_float2(v[0], v[1]);
        }
    }
}

// ---------------- launch ----------------
extern "C" void kernel_launch(void* const* d_in, const int* in_sizes, int n_in,
                              void* d_out, int out_size) {
    const float* x = (const float*)d_in[0];
    const void* ei = d_in[1];
    const float* w1 = (const float*)d_in[2];
    const float* as1 = (const float*)d_in[3];
    const float* ad1 = (const float*)d_in[4];
    const float* b1 = (const float*)d_in[5];
    const float* w2 = (const float*)d_in[6];
    const float* as2 = (const float*)d_in[7];
    const float* ad2 = (const float*)d_in[8];
    const float* b2 = (const float*)d_in[9];
    const float* w3 = (const float*)d_in[10];
    const float* as3 = (const float*)d_in[11];
    const float* ad3 = (const float*)d_in[12];
    const float* b3 = (const float*)d_in[13];
    const float* w4 = (const float*)d_in[14];
    const float* as4 = (const float*)d_in[15];
    const float* ad4 = (const float*)d_in[16];
    const float* b4 = (const float*)d_in[17];

    int n = in_sizes[0] / 64;
    int eraw = in_sizes[1] / 2;
    int etot = eraw + n;

    float* out_sec = (float*)d_out;         // [n*64]
    float* h_sec = (float*)d_out + n * 64;  // [n*32]

    int nbE = (etot + 255) / 256;
    int nbN = (n + 255) / 256;
    int nbW = (n * 32 + 511) / 512;
    int nblk = (n + 1023) / 1024;

    // graph prep (once per call)
    k_detect<<<1, 128>>>((const unsigned int*)ei, in_sizes[1]);
    k_convert<<<nbE, 256>>>(ei, eraw, n);
    k_zero<<<nbN, 256>>>(n);
    k_hist<<<nbE, 256>>>(etot);
    k_scan_bt<<<nblk, 256>>>(n);
    k_scan_mid<<<1, 32>>>(nblk, n);
    k_scan_wr<<<nblk, 256>>>(n);
    k_scatter<<<nbE, 256>>>(etot);

    // layer 1: x 64->64, relu -> featA
    k_gemm_sc<64, 64><<<nbW, 512>>>(0, x, w1, as1, ad1, n);
    k_edgepre<<<nbE, 256>>>(etot);
    k_gather<64><<<nbW, 512>>>(b1, 1, nullptr, n);

    // layer 2: featA 64->32, raw h -> d_out, relu -> featB
    k_gemm_sc<64, 32><<<nbW, 512>>>(1, nullptr, w2, as2, ad2, n);
    k_edgepre<<<nbE, 256>>>(etot);
    k_gather<32><<<nbW, 512>>>(b2, 2, h_sec, n);

    // layer 3: featB 32->64, relu -> featA
    k_gemm_sc<32, 64><<<nbW, 512>>>(2, nullptr, w3, as3, ad3, n);
    k_edgepre<<<nbE, 256>>>(etot);
    k_gather<64><<<nbW, 512>>>(b3, 1, nullptr, n);

    // layer 4: featA 64->64, raw -> d_out
    k_gemm_sc<64, 64><<<nbW, 512>>>(1, nullptr, w4, as4, ad4, n);
    k_edgepre<<<nbE, 256>>>(etot);
    k_gather<64><<<nbW, 512>>>(b4, 0, out_sec, n);
}

// round 10
// speedup vs baseline: 1.3036x; 1.0592x over previous
#include <cuda_runtime.h>
#include <math_constants.h>

// GAT autoencoder, CSR-gather formulation.
// Layers: 64->64 relu, 64->32 [h out], relu, 32->64 relu, 64->64 [out].
// Outputs concatenated: out [N*64] then h [N*32].

#define MAXN 50000
#define MAXE 800000
#define MAXET (MAXE + MAXN)
#define MAXBLK 64
#define STASH 80  // per-warp smem logit stash (deg > STASH falls back to g_e)

// ---------------- scratch ----------------
__device__ __align__(16) float g_featA[MAXN * 64];
__device__ __align__(16) float g_featB[MAXN * 64];
__device__ __align__(16) float g_h[MAXN * 64];
__device__ float g_ssrc[MAXN];
__device__ float g_sdst[MAXN];
__device__ float g_e[MAXET];  // fallback only (deg > STASH)
__device__ int g_src[MAXET];
__device__ int g_dst[MAXET];
__device__ int g_adj[MAXET];
__device__ int g_roff[MAXN + 1];
__device__ int g_cnt[MAXN];
__device__ int g_cur[MAXN];
__device__ int g_bt[MAXBLK];
__device__ int g_boff[MAXBLK];
__device__ int g_is64;

__device__ __forceinline__ const float* pick_src(int sel, const float* ext) {
    if (sel == 1) return g_featA;
    if (sel == 2) return g_featB;
    return ext;
}
__device__ __forceinline__ float* pick_dst(int sel) {
    if (sel == 1) return g_featA;
    if (sel == 2) return g_featB;
    return nullptr;
}

// ---------------- graph prep ----------------

// parallel dtype detect: int64 little-endian ids < 2^31 => odd words all 0
__global__ void k_detect(const unsigned int* __restrict__ w, int nelem) {
    __shared__ int bad;
    if (threadIdx.x == 0) bad = 0;
    __syncthreads();
    int idx = 2 * (int)threadIdx.x + 1;
    if (idx < 2 * nelem && idx < 256 && w[idx] != 0) atomicOr(&bad, 1);
    __syncthreads();
    if (threadIdx.x == 0) g_is64 = !bad;
}

__global__ void k_zero(int n) {
    int i = blockIdx.x * 256 + threadIdx.x;
    if (i < n) g_cnt[i] = 0;
}

// convert + degree histogram fused (saves a full pass over g_dst)
__global__ void k_convert(const void* __restrict__ ei, int eraw, int n) {
    int i = blockIdx.x * 256 + threadIdx.x;
    int etot = eraw + n;
    if (i >= etot) return;
    int s, d;
    if (i < eraw) {
        if (g_is64) {
            const long long* p = (const long long*)ei;
            s = (int)p[i];
            d = (int)p[eraw + i];
        } else {
            const int* p = (const int*)ei;
            s = p[i];
            d = p[eraw + i];
        }
        s = s < 0 ? 0 : (s >= n ? n - 1 : s);
        d = d < 0 ? 0 : (d >= n ? n - 1 : d);
    } else {
        s = d = i - eraw;
    }
    g_src[i] = s;
    g_dst[i] = d;
    atomicAdd(&g_cnt[d], 1);
}

// --- two-level exclusive scan of g_cnt ---
__global__ void k_scan_bt(int n) {
    int base = blockIdx.x * 1024;
    int i0 = base + threadIdx.x * 4;
    int t = 0;
#pragma unroll
    for (int c = 0; c < 4; c++) t += (i0 + c < n) ? g_cnt[i0 + c] : 0;
    int lane = threadIdx.x & 31, wid = threadIdx.x >> 5;
#pragma unroll
    for (int off = 16; off; off >>= 1) t += __shfl_xor_sync(~0u, t, off);
    __shared__ int ws[8];
    if (lane == 0) ws[wid] = t;
    __syncthreads();
    if (threadIdx.x == 0) {
        int s = 0;
#pragma unroll
        for (int w = 0; w < 8; w++) s += ws[w];
        g_bt[blockIdx.x] = s;
    }
}

__global__ void k_scan_mid(int nblk, int n) {
    int lane = threadIdx.x;
    int carry = 0;
    for (int base = 0; base < nblk; base += 32) {
        int i = base + lane;
        int v = (i < nblk) ? g_bt[i] : 0;
        int incl = v;
#pragma unroll
        for (int off = 1; off < 32; off <<= 1) {
            int t = __shfl_up_sync(~0u, incl, off);
            if (lane >= off) incl += t;
        }
        if (i < nblk) g_boff[i] = carry + incl - v;
        carry += __shfl_sync(~0u, incl, 31);
    }
    if (lane == 0) g_roff[n] = carry;
}

__global__ void k_scan_wr(int n) {
    int base = blockIdx.x * 1024;
    int i0 = base + threadIdx.x * 4;
    int v[4], tsum = 0;
#pragma unroll
    for (int c = 0; c < 4; c++) {
        v[c] = (i0 + c < n) ? g_cnt[i0 + c] : 0;
        tsum += v[c];
    }
    int lane = threadIdx.x & 31, wid = threadIdx.x >> 5;
    int incl = tsum;
#pragma unroll
    for (int off = 1; off < 32; off <<= 1) {
        int t = __shfl_up_sync(~0u, incl, off);
        if (lane >= off) incl += t;
    }
    __shared__ int ws[8];
    if (lane == 31) ws[wid] = incl;
    __syncthreads();
    int woff = 0;
    for (int w = 0; w < wid; w++) woff += ws[w];
    int ex = g_boff[blockIdx.x] + woff + incl - tsum;
#pragma unroll
    for (int c = 0; c < 4; c++) {
        if (i0 + c < n) {
            g_roff[i0 + c] = ex;
            g_cur[i0 + c] = ex;
            ex += v[c];
        }
    }
}

__global__ void k_scatter(int etot) {
    int i = blockIdx.x * 256 + threadIdx.x;
    if (i >= etot) return;
    int pos = atomicAdd(&g_cur[g_dst[i]], 1);
    g_adj[pos] = g_src[i];
}

// ---------------- fused gemm + attention scores ----------------
template <int DI, int DO>
__global__ void k_gemm_sc(int xsel, const float* __restrict__ xext,
                          const float* __restrict__ W,
                          const float* __restrict__ as_,
                          const float* __restrict__ ad_, int n) {
    __shared__ float Ws[DI * DO];
    for (int i = threadIdx.x; i < DI * DO; i += blockDim.x) Ws[i] = W[i];
    __syncthreads();
    int row = (blockIdx.x * blockDim.x + threadIdx.x) >> 5;
    int lane = threadIdx.x & 31;
    if (row >= n) return;
    const float* x = pick_src(xsel, xext) + row * DI;
    float acc0 = 0.f, acc1 = 0.f;
#pragma unroll
    for (int k0 = 0; k0 < DI; k0 += 32) {
        float xv = x[k0 + lane];
#pragma unroll
        for (int kk = 0; kk < 32; kk++) {
            float xk = __shfl_sync(0xFFFFFFFFu, xv, kk);
            acc0 = fmaf(xk, Ws[(k0 + kk) * DO + lane], acc0);
            if (DO == 64) acc1 = fmaf(xk, Ws[(k0 + kk) * DO + lane + 32], acc1);
        }
    }
    g_h[row * DO + lane] = acc0;
    if (DO == 64) g_h[row * DO + lane + 32] = acc1;
    float ss = acc0 * __ldg(as_ + lane);
    float sd = acc0 * __ldg(ad_ + lane);
    if (DO == 64) {
        ss = fmaf(acc1, __ldg(as_ + lane + 32), ss);
        sd = fmaf(acc1, __ldg(ad_ + lane + 32), sd);
    }
#pragma unroll
    for (int off = 16; off; off >>= 1) {
        ss += __shfl_xor_sync(0xFFFFFFFFu, ss, off);
        sd += __shfl_xor_sync(0xFFFFFFFFu, sd, off);
    }
    if (lane == 0) {
        g_ssrc[row] = ss;
        g_sdst[row] = sd;
    }
}

// ---------------- fused softmax + aggregation ----------------
// warp per dst node. Pass 1 computes leaky logits from adj+ssrc (edgepre
// fused), stashing them in smem (STASH slots/warp; spill to g_e beyond)
// while reducing the max. Pass 2: two half-warps, alternating edges.
template <int DO>
__global__ void k_gather(const float* __restrict__ b, int featsel,
                         float* __restrict__ raw, int n) {
    const int C = DO / 16;  // 4 (DO=64) or 2 (DO=32)
    __shared__ float es[16][STASH];
    int wslot = threadIdx.x >> 5;
    int d = (blockIdx.x * blockDim.x + threadIdx.x) >> 5;
    int lane = threadIdx.x & 31;
    int half = lane >> 4, l16 = lane & 15;
    if (d >= n) return;
    int r0 = __ldg(&g_roff[d]);
    int r1 = __ldg(&g_roff[d + 1]);
    float sd = g_sdst[d];

    // pass 1: compute leaky logits, stash, reduce max
    float m = -CUDART_INF_F;
    for (int j = r0 + lane; j < r1; j += 32) {
        int s = __ldg(&g_adj[j]);
        float e = __ldg(&g_ssrc[s]) + sd;
        e = e > 0.f ? e : 0.2f * e;
        int k = j - r0;
        if (k < STASH) es[wslot][k] = e;
        else g_e[j] = e;
        m = fmaxf(m, e);
    }
#pragma unroll
    for (int off = 16; off; off >>= 1)
        m = fmaxf(m, __shfl_xor_sync(0xFFFFFFFFu, m, off));
    __syncwarp();

    // pass 2: each half-warp handles alternating edges
    float den = 0.f;
    float acc[C];
#pragma unroll
    for (int c = 0; c < C; c++) acc[c] = 0.f;
    for (int j = r0 + half; j < r1; j += 2) {
        int k = j - r0;
        float e = (k < STASH) ? es[wslot][k] : g_e[j];
        int s = __ldg(&g_adj[j]);
        float ex = __expf(e - m);
        den += ex;
        float hv[C];
        if (C == 4) {
            float4 t = __ldg(reinterpret_cast<const float4*>(g_h + s * DO) + l16);
            hv[0] = t.x; hv[1] = t.y; hv[2] = t.z; hv[3] = t.w;
        } else {
            float2 t = __ldg(reinterpret_cast<const float2*>(g_h + s * DO) + l16);
            hv[0] = t.x; hv[1] = t.y;
        }
#pragma unroll
        for (int c = 0; c < C; c++) acc[c] = fmaf(ex, hv[c], acc[c]);
    }
    // merge the two halves
    den += __shfl_xor_sync(0xFFFFFFFFu, den, 16);
#pragma unroll
    for (int c = 0; c < C; c++) acc[c] += __shfl_xor_sync(0xFFFFFFFFu, acc[c], 16);

    if (half == 0) {
        float inv = 1.f / (den + 1e-16f);
        float v[C];
#pragma unroll
        for (int c = 0; c < C; c++)
            v[c] = acc[c] * inv + __ldg(b + l16 * C + c);
        float* feat = pick_dst(featsel);
        if (raw) {
            if (C == 4)
                reinterpret_cast<float4*>(raw + d * DO)[l16] =
                    make_float4(v[0], v[1], v[2], v[3]);
            else
                reinterpret_cast<float2*>(raw + d * DO)[l16] =
                    make_float2(v[0], v[1]);
        }
        if (feat) {
#pragma unroll
            for (int c = 0; c < C; c++) v[c] = v[c] > 0.f ? v[c] : 0.f;
            if (C == 4)
                reinterpret_cast<float4*>(feat + d * DO)[l16] =
                    make_float4(v[0], v[1], v[2], v[3]);
            else
                reinterpret_cast<float2*>(feat + d * DO)[l16] =
                    make_float2(v[0], v[1]);
        }
    }
}

// ---------------- launch ----------------
extern "C" void kernel_launch(void* const* d_in, const int* in_sizes, int n_in,
                              void* d_out, int out_size) {
    const float* x = (const float*)d_in[0];
    const void* ei = d_in[1];
    const float* w1 = (const float*)d_in[2];
    const float* as1 = (const float*)d_in[3];
    const float* ad1 = (const float*)d_in[4];
    const float* b1 = (const float*)d_in[5];
    const float* w2 = (const float*)d_in[6];
    const float* as2 = (const float*)d_in[7];
    const float* ad2 = (const float*)d_in[8];
    const float* b2 = (const float*)d_in[9];
    const float* w3 = (const float*)d_in[10];
    const float* as3 = (const float*)d_in[11];
    const float* ad3 = (const float*)d_in[12];
    const float* b3 = (const float*)d_in[13];
    const float* w4 = (const float*)d_in[14];
    const float* as4 = (const float*)d_in[15];
    const float* ad4 = (const float*)d_in[16];
    const float* b4 = (const float*)d_in[17];

    int n = in_sizes[0] / 64;
    int eraw = in_sizes[1] / 2;
    int etot = eraw + n;

    float* out_sec = (float*)d_out;         // [n*64]
    float* h_sec = (float*)d_out + n * 64;  // [n*32]

    int nbE = (etot + 255) / 256;
    int nbN = (n + 255) / 256;
    int nbW = (n * 32 + 511) / 512;
    int nblk = (n + 1023) / 1024;

    // graph prep (once per call)
    k_detect<<<1, 128>>>((const unsigned int*)ei, in_sizes[1]);
    k_zero<<<nbN, 256>>>(n);
    k_convert<<<nbE, 256>>>(ei, eraw, n);
    k_scan_bt<<<nblk, 256>>>(n);
    k_scan_mid<<<1, 32>>>(nblk, n);
    k_scan_wr<<<nblk, 256>>>(n);
    k_scatter<<<nbE, 256>>>(etot);

    // layer 1: x 64->64, relu -> featA
    k_gemm_sc<64, 64><<<nbW, 512>>>(0, x, w1, as1, ad1, n);
    k_gather<64><<<nbW, 512>>>(b1, 1, nullptr, n);

    // layer 2: featA 64->32, raw h -> d_out, relu -> featB
    k_gemm_sc<64, 32><<<nbW, 512>>>(1, nullptr, w2, as2, ad2, n);
    k_gather<32><<<nbW, 512>>>(b2, 2, h_sec, n);

    // layer 3: featB 32->64, relu -> featA
    k_gemm_sc<32, 64><<<nbW, 512>>>(2, nullptr, w3, as3, ad3, n);
    k_gather<64><<<nbW, 512>>>(b3, 1, nullptr, n);

    // layer 4: featA 64->64, raw -> d_out
    k_gemm_sc<64, 64><<<nbW, 512>>>(1, nullptr, w4, as4, ad4, n);
    k_gather<64><<<nbW, 512>>>(b4, 0, out_sec, n);
}